// round 2
// baseline (speedup 1.0000x reference)
#include <cuda_runtime.h>
#include <math.h>

#define T_STEPS 4096
#define HID     4096
#define IN_SZ   1024
#define OUT_SZ  512
#define LEAK    0.1f
#define S_CACHE 12          // weight rows cached in smem per CTA

// Scratch (device globals: allocation-free rule)
__device__ float g_I  [(size_t)T_STEPS * HID];   // 64 MB: precomputed W_in @ x_t
__device__ float g_Hst[(size_t)T_STEPS * HID];   // 64 MB: h_t history (input to Y GEMM)
__device__ unsigned g_count = 0;
__device__ unsigned g_sense = 0;

// ---------------------------------------------------------------------------
// Simple register-blocked SGEMM, C[M,N] = A[M,K] * B[N,K]^T  (both K-major)
// BM=BN=128, BK=16, 256 threads, 8x8 per thread. M,N % 128 == 0, K % 16 == 0.
// ---------------------------------------------------------------------------
__global__ void __launch_bounds__(256, 1) sgemm_nt(
    int M, int N, int K,
    const float* __restrict__ A, const float* __restrict__ B,
    float* __restrict__ C)
{
    __shared__ float As[16 * 136];
    __shared__ float Bs[16 * 136];
    const int bm = blockIdx.y * 128;
    const int bn = blockIdx.x * 128;
    const int tid = threadIdx.x;
    const int tx = tid & 15;        // 16 col-tiles
    const int ty = tid >> 4;        // 16 row-tiles

    float acc[8][8];
#pragma unroll
    for (int i = 0; i < 8; i++)
#pragma unroll
        for (int j = 0; j < 8; j++) acc[i][j] = 0.f;

    for (int k0 = 0; k0 < K; k0 += 16) {
        float4 av[2], bv[2];
#pragma unroll
        for (int u = 0; u < 2; u++) {
            int li = tid + u * 256;            // 0..511
            int r   = li >> 2;                 // tile row 0..127
            int kc4 = li & 3;                  // float4 within 16 k's
            av[u] = *(const float4*)(A + (size_t)(bm + r) * K + k0 + kc4 * 4);
            bv[u] = *(const float4*)(B + (size_t)(bn + r) * K + k0 + kc4 * 4);
        }
        __syncthreads();
#pragma unroll
        for (int u = 0; u < 2; u++) {
            int li = tid + u * 256;
            int r   = li >> 2;
            int kc4 = li & 3;
            As[(kc4 * 4 + 0) * 136 + r] = av[u].x;
            As[(kc4 * 4 + 1) * 136 + r] = av[u].y;
            As[(kc4 * 4 + 2) * 136 + r] = av[u].z;
            As[(kc4 * 4 + 3) * 136 + r] = av[u].w;
            Bs[(kc4 * 4 + 0) * 136 + r] = bv[u].x;
            Bs[(kc4 * 4 + 1) * 136 + r] = bv[u].y;
            Bs[(kc4 * 4 + 2) * 136 + r] = bv[u].z;
            Bs[(kc4 * 4 + 3) * 136 + r] = bv[u].w;
        }
        __syncthreads();
#pragma unroll
        for (int kk = 0; kk < 16; kk++) {
            float ra[8], rb[8];
            *(float4*)&ra[0] = *(const float4*)&As[kk * 136 + ty * 8];
            *(float4*)&ra[4] = *(const float4*)&As[kk * 136 + ty * 8 + 4];
            *(float4*)&rb[0] = *(const float4*)&Bs[kk * 136 + tx * 8];
            *(float4*)&rb[4] = *(const float4*)&Bs[kk * 136 + tx * 8 + 4];
#pragma unroll
            for (int i = 0; i < 8; i++)
#pragma unroll
                for (int j = 0; j < 8; j++)
                    acc[i][j] = fmaf(ra[i], rb[j], acc[i][j]);
        }
        __syncthreads();
    }

#pragma unroll
    for (int i = 0; i < 8; i++) {
        float* cp = C + (size_t)(bm + ty * 8 + i) * N + bn + tx * 8;
        *(float4*)(cp    ) = make_float4(acc[i][0], acc[i][1], acc[i][2], acc[i][3]);
        *(float4*)(cp + 4) = make_float4(acc[i][4], acc[i][5], acc[i][6], acc[i][7]);
    }
}

// ---------------------------------------------------------------------------
// Sequential scan: persistent kernel, one CTA per SM, grid barrier per step.
// Each CTA owns `rpc` rows of W_rec; first S_CACHE rows live in smem, the
// rest stream from L2 (W_rec is L2-resident: reused every ~4us).
// ---------------------------------------------------------------------------
__device__ __forceinline__ float dot_row(const float4* __restrict__ w4,
                                         const float4* __restrict__ h4,
                                         int lane)
{
    float ax = 0.f, ay = 0.f, az = 0.f, aw = 0.f;
#pragma unroll 4
    for (int k = lane; k < HID / 4; k += 32) {
        float4 a = w4[k];
        float4 b = h4[k];
        ax = fmaf(a.x, b.x, ax);
        ay = fmaf(a.y, b.y, ay);
        az = fmaf(a.z, b.z, az);
        aw = fmaf(a.w, b.w, aw);
    }
    float r = (ax + ay) + (az + aw);
#pragma unroll
    for (int o = 16; o; o >>= 1) r += __shfl_xor_sync(0xffffffffu, r, o);
    return r;
}

__global__ void __launch_bounds__(1024, 1) scan_kernel(
    const float* __restrict__ W_rec,
    const float* __restrict__ G_bias,
    int G, int rpc)
{
    extern __shared__ float sm[];
    float* h_s = sm;                 // HID floats: current h broadcast
    float* w_s = sm + HID;           // S_CACHE*HID floats: cached weight rows

    const int tid  = threadIdx.x;
    const int cta  = blockIdx.x;
    const int row0 = cta * rpc;
    int nrows = HID - row0;
    if (nrows > rpc) nrows = rpc;
    if (nrows < 0)  nrows = 0;
    const int sc = nrows < S_CACHE ? nrows : S_CACHE;

    // Preload cached weight rows (once)
    {
        const float4* src = (const float4*)(W_rec + (size_t)row0 * HID);
        float4* dst = (float4*)w_s;
        const int n4 = sc * (HID / 4);
        for (int i = tid; i < n4; i += 1024) dst[i] = src[i];
    }

    const int warp = tid >> 5;
    const int lane = tid & 31;
    unsigned sense = 0;
    float4* h_s4 = (float4*)h_s;

    for (int t = 0; t < T_STEPS; t++) {
        // Broadcast h_{t-1} into smem
        if (t == 0) {
            for (int i = tid; i < HID / 4; i += 1024)
                h_s4[i] = make_float4(0.f, 0.f, 0.f, 0.f);
        } else {
            const float4* hp = (const float4*)(g_Hst + (size_t)(t - 1) * HID);
            for (int i = tid; i < HID / 4; i += 1024) h_s4[i] = hp[i];
        }
        __syncthreads();

        // Each warp computes its rows (one per warp when rpc <= 32)
        for (int rr = warp; rr < nrows; rr += 32) {
            const int row = row0 + rr;
            float r;
            if (rr < sc) {
                r = dot_row((const float4*)(w_s + (size_t)rr * HID),
                            (const float4*)h_s, lane);
            } else {
                r = dot_row((const float4*)(W_rec + (size_t)row * HID),
                            (const float4*)h_s, lane);
            }
            if (lane == 0) {
                const float it   = g_I[(size_t)t * HID + row];
                const float hold = h_s[row];
                const float gate = 1.f / (1.f + expf(-(G_bias[row] + r)));
                const float z    = tanhf(fmaf(gate, r, it));
                const float hnew = fmaf(LEAK, z - hold, hold);
                g_Hst[(size_t)t * HID + row] = hnew;
            }
        }

        // ---- grid barrier (sense-reversing; state returns to 0: 4096 even) ----
        __syncthreads();
        if (tid == 0) {
            const unsigned target = sense ^ 1u;
            __threadfence();
            if (atomicAdd(&g_count, 1u) == (unsigned)G - 1u) {
                g_count = 0u;
                __threadfence();
                atomicExch(&g_sense, target);
            } else {
                volatile unsigned* vs = &g_sense;
                while (*vs != target) { }
                __threadfence();
            }
        }
        sense ^= 1u;
        __syncthreads();
    }
}

// ---------------------------------------------------------------------------
extern "C" void kernel_launch(void* const* d_in, const int* in_sizes, int n_in,
                              void* d_out, int out_size)
{
    const float* x     = (const float*)d_in[0];  // [T, 1024]
    const float* W_in  = (const float*)d_in[1];  // [4096, 1024]
    const float* W_rec = (const float*)d_in[2];  // [4096, 4096]
    const float* W_out = (const float*)d_in[3];  // [512, 4096]
    const float* G_b   = (const float*)d_in[4];  // [4096]
    float* y = (float*)d_out;                    // [T, 512]

    int smCount = 0;
    cudaDeviceGetAttribute(&smCount, cudaDevAttrMultiProcessorCount, 0);
    if (smCount < 128) smCount = 148;            // fallback; GB300 = 152
    const int G   = smCount;
    const int rpc = (HID + G - 1) / G;

    float *pI = nullptr, *pH = nullptr;
    cudaGetSymbolAddress((void**)&pI, g_I);
    cudaGetSymbolAddress((void**)&pH, g_Hst);

    const size_t smem = (size_t)(S_CACHE + 1) * HID * sizeof(float); // 208 KB
    cudaFuncSetAttribute(scan_kernel, cudaFuncAttributeMaxDynamicSharedMemorySize,
                         (int)smem);

    // Phase 1: I = x @ W_in^T   [4096 x 4096]
    dim3 g1(HID / 128, T_STEPS / 128);
    sgemm_nt<<<g1, 256>>>(T_STEPS, HID, IN_SZ, x, W_in, pI);

    // Phase 2: sequential gated leaky scan (persistent, grid-synced)
    scan_kernel<<<G, 1024, smem>>>(W_rec, G_b, G, rpc);

    // Phase 3: Y = H @ W_out^T  [4096 x 512]
    dim3 g2(OUT_SZ / 128, T_STEPS / 128);
    sgemm_nt<<<g2, 256>>>(T_STEPS, OUT_SZ, HID, pH, W_out, y);
}

// round 3
// speedup vs baseline: 1.0652x; 1.0652x over previous
#include <cuda_runtime.h>
#include <cuda_fp16.h>
#include <math.h>

#define T_STEPS 4096
#define HID     4096
#define IN_SZ   1024
#define OUT_SZ  512
#define LEAK    0.1f

// Scratch (device globals: allocation-free rule)
__device__ float g_I  [(size_t)T_STEPS * HID];   // 64 MB: precomputed W_in @ x_t
__device__ float g_Hst[(size_t)T_STEPS * HID];   // 64 MB: h_t history (input to Y GEMM)
__device__ unsigned g_count = 0;
__device__ unsigned g_sense = 0;

// ---------------------------------------------------------------------------
// Register-blocked SGEMM, C[M,N] = A[M,K] * B[N,K]^T (both K-major).
// BM=BN=128, BK=16, 256 threads, 8x8 per thread.
// ---------------------------------------------------------------------------
__global__ void __launch_bounds__(256, 1) sgemm_nt(
    int M, int N, int K,
    const float* __restrict__ A, const float* __restrict__ B,
    float* __restrict__ C)
{
    __shared__ float As[16 * 136];
    __shared__ float Bs[16 * 136];
    const int bm = blockIdx.y * 128;
    const int bn = blockIdx.x * 128;
    const int tid = threadIdx.x;
    const int tx = tid & 15;
    const int ty = tid >> 4;

    float acc[8][8];
#pragma unroll
    for (int i = 0; i < 8; i++)
#pragma unroll
        for (int j = 0; j < 8; j++) acc[i][j] = 0.f;

    for (int k0 = 0; k0 < K; k0 += 16) {
        float4 av[2], bv[2];
#pragma unroll
        for (int u = 0; u < 2; u++) {
            int li = tid + u * 256;
            int r   = li >> 2;
            int kc4 = li & 3;
            av[u] = *(const float4*)(A + (size_t)(bm + r) * K + k0 + kc4 * 4);
            bv[u] = *(const float4*)(B + (size_t)(bn + r) * K + k0 + kc4 * 4);
        }
        __syncthreads();
#pragma unroll
        for (int u = 0; u < 2; u++) {
            int li = tid + u * 256;
            int r   = li >> 2;
            int kc4 = li & 3;
            As[(kc4 * 4 + 0) * 136 + r] = av[u].x;
            As[(kc4 * 4 + 1) * 136 + r] = av[u].y;
            As[(kc4 * 4 + 2) * 136 + r] = av[u].z;
            As[(kc4 * 4 + 3) * 136 + r] = av[u].w;
            Bs[(kc4 * 4 + 0) * 136 + r] = bv[u].x;
            Bs[(kc4 * 4 + 1) * 136 + r] = bv[u].y;
            Bs[(kc4 * 4 + 2) * 136 + r] = bv[u].z;
            Bs[(kc4 * 4 + 3) * 136 + r] = bv[u].w;
        }
        __syncthreads();
#pragma unroll
        for (int kk = 0; kk < 16; kk++) {
            float ra[8], rb[8];
            *(float4*)&ra[0] = *(const float4*)&As[kk * 136 + ty * 8];
            *(float4*)&ra[4] = *(const float4*)&As[kk * 136 + ty * 8 + 4];
            *(float4*)&rb[0] = *(const float4*)&Bs[kk * 136 + tx * 8];
            *(float4*)&rb[4] = *(const float4*)&Bs[kk * 136 + tx * 8 + 4];
#pragma unroll
            for (int i = 0; i < 8; i++)
#pragma unroll
                for (int j = 0; j < 8; j++)
                    acc[i][j] = fmaf(ra[i], rb[j], acc[i][j]);
        }
        __syncthreads();
    }

#pragma unroll
    for (int i = 0; i < 8; i++) {
        float* cp = C + (size_t)(bm + ty * 8 + i) * N + bn + tx * 8;
        *(float4*)(cp    ) = make_float4(acc[i][0], acc[i][1], acc[i][2], acc[i][3]);
        *(float4*)(cp + 4) = make_float4(acc[i][4], acc[i][5], acc[i][6], acc[i][7]);
    }
}

// ---------------------------------------------------------------------------
// Scan v2: the entire W_rec slice of each CTA lives in smem as fp16.
// Column-partitioned matvec: 32 warps = 8 j-groups (512 cols) x 4 row-groups.
// h slice held in registers (16 floats/lane), loaded once per step from L2.
// Partial sums combined via warp shuffles + tiny smem buffer.
// ---------------------------------------------------------------------------
__global__ void __launch_bounds__(1024, 1) scan_fp16(
    const float* __restrict__ W_rec,
    const float* __restrict__ G_bias,
    int G, int rpc)
{
    extern __shared__ char smem_raw[];
    __half* w_s  = (__half*)smem_raw;                              // rpc*HID halves
    float*  part = (float*)(smem_raw + (size_t)rpc * HID * 2);     // rpc*8 floats

    const int tid  = threadIdx.x;
    const int cta  = blockIdx.x;
    const int row0 = cta * rpc;
    int nrows = HID - row0;
    if (nrows > rpc) nrows = rpc;
    if (nrows < 0)  nrows = 0;

    // One-time: load this CTA's W_rec rows, convert fp32 -> fp16 into smem.
    {
        const float4* src = (const float4*)(W_rec + (size_t)row0 * HID);
        const int n4 = nrows * (HID / 4);
        for (int i = tid; i < n4; i += 1024) {
            float4 v = src[i];
            __half2* d = (__half2*)w_s + (size_t)i * 2;
            d[0] = __floats2half2_rn(v.x, v.y);
            d[1] = __floats2half2_rn(v.z, v.w);
        }
    }
    __syncthreads();

    const int warp = tid >> 5;
    const int lane = tid & 31;
    const int jg   = warp & 7;          // 8 j-groups of 512 columns
    const int rg   = warp >> 3;         // 4 row-groups
    const int chunk = (nrows + 3) >> 2;
    const int rlo = rg * chunk;
    int rhi = rlo + chunk;
    if (rhi > nrows) rhi = nrows;

    // Per-thread epilogue state: thread tid owns row (row0 + tid) forever.
    const int myrow = row0 + tid;
    float hOld = 0.f, gbias = 0.f;
    if (tid < nrows) gbias = G_bias[myrow];

    const int hbase = jg * 512 + lane * 16;
    unsigned sense = 0;

    for (int t = 0; t < T_STEPS; ++t) {
        // Prefetch the epilogue's I value early (hidden behind compute).
        float Ival = 0.f;
        if (tid < nrows) Ival = g_I[(size_t)t * HID + myrow];

        // Load this warp's 512-wide h slice into registers (16 floats/lane).
        float h[16];
        if (t == 0) {
#pragma unroll
            for (int k = 0; k < 16; ++k) h[k] = 0.f;
        } else {
            const float4* hp = (const float4*)(g_Hst + (size_t)(t - 1) * HID + hbase);
#pragma unroll
            for (int q = 0; q < 4; ++q) {
                float4 v = hp[q];
                h[q * 4 + 0] = v.x; h[q * 4 + 1] = v.y;
                h[q * 4 + 2] = v.z; h[q * 4 + 3] = v.w;
            }
        }

        // Partial dot products for this warp's rows over its j slice.
        for (int r = rlo; r < rhi; ++r) {
            const uint4* wp = (const uint4*)(w_s + (size_t)r * HID + hbase);
            uint4 a = wp[0];
            uint4 b = wp[1];
            unsigned wb[8] = {a.x, a.y, a.z, a.w, b.x, b.y, b.z, b.w};
            float acc0 = 0.f, acc1 = 0.f;
#pragma unroll
            for (int q = 0; q < 8; ++q) {
                float2 f = __half22float2(*(__half2*)&wb[q]);
                acc0 = fmaf(f.x, h[2 * q + 0], acc0);
                acc1 = fmaf(f.y, h[2 * q + 1], acc1);
            }
            float acc = acc0 + acc1;
#pragma unroll
            for (int o = 16; o; o >>= 1) acc += __shfl_xor_sync(0xffffffffu, acc, o);
            if (lane == 0) part[r * 8 + jg] = acc;
        }
        __syncthreads();

        // Epilogue: thread tid finalizes its row.
        if (tid < nrows) {
            float rsum = 0.f;
#pragma unroll
            for (int q = 0; q < 8; ++q) rsum += part[tid * 8 + q];
            const float gate = 1.f / (1.f + expf(-(gbias + rsum)));
            const float z    = tanhf(fmaf(gate, rsum, Ival));
            hOld = fmaf(LEAK, z - hOld, hOld);
            g_Hst[(size_t)t * HID + myrow] = hOld;
        }

        // Grid barrier (sense-reversing). Also fences part[] reuse.
        __syncthreads();
        if (tid == 0) {
            const unsigned target = sense ^ 1u;
            __threadfence();
            if (atomicAdd(&g_count, 1u) == (unsigned)G - 1u) {
                g_count = 0u;
                __threadfence();
                atomicExch(&g_sense, target);
            } else {
                volatile unsigned* vs = &g_sense;
                while (*vs != target) { }
                __threadfence();
            }
        }
        sense ^= 1u;
        __syncthreads();
    }
}

// ---------------------------------------------------------------------------
extern "C" void kernel_launch(void* const* d_in, const int* in_sizes, int n_in,
                              void* d_out, int out_size)
{
    const float* x     = (const float*)d_in[0];  // [T, 1024]
    const float* W_in  = (const float*)d_in[1];  // [4096, 1024]
    const float* W_rec = (const float*)d_in[2];  // [4096, 4096]
    const float* W_out = (const float*)d_in[3];  // [512, 4096]
    const float* G_b   = (const float*)d_in[4];  // [4096]
    float* y = (float*)d_out;                    // [T, 512]

    int smCount = 0;
    cudaDeviceGetAttribute(&smCount, cudaDevAttrMultiProcessorCount, 0);
    if (smCount < 128) smCount = 152;            // GB300 = 152 SMs
    const int G   = smCount;
    const int rpc = (HID + G - 1) / G;           // 27 @ 152 SMs (28 @ 148)

    float *pI = nullptr, *pH = nullptr;
    cudaGetSymbolAddress((void**)&pI, g_I);
    cudaGetSymbolAddress((void**)&pH, g_Hst);

    // fp16 weights + partial buffer. rpc=27 -> 222,048 B (< 227 KB limit).
    const size_t smem = (size_t)rpc * HID * 2 + (size_t)rpc * 8 * 4;
    cudaFuncSetAttribute(scan_fp16, cudaFuncAttributeMaxDynamicSharedMemorySize,
                         (int)smem);

    // Phase 1: I = x @ W_in^T   [4096 x 4096]
    dim3 g1(HID / 128, T_STEPS / 128);
    sgemm_nt<<<g1, 256>>>(T_STEPS, HID, IN_SZ, x, W_in, pI);

    // Phase 2: sequential gated leaky scan (persistent, grid-synced)
    scan_fp16<<<G, 1024, smem>>>(W_rec, G_b, G, rpc);

    // Phase 3: Y = H @ W_out^T  [4096 x 512]
    dim3 g2(OUT_SZ / 128, T_STEPS / 128);
    sgemm_nt<<<g2, 256>>>(T_STEPS, OUT_SZ, HID, pH, W_out, y);
}